// round 10
// baseline (speedup 1.0000x reference)
#include <cuda_runtime.h>
#include <cstdint>
#include <math.h>

// ============================================================================
// W8A8 int8 GEMM + alpha/bias + SiLU -> fp32   (base sm_103 ISA: no tcgen05)
//   x [8192,4096] i8 (K-major), w [11008,4096] i8 (K-major), out [8192,11008] f32
//
// R10: (a) 3-launch structure (detect folded into pack) so ncu -s 5 captures
// the GEMM, not pack; (b) revert to R8 config (3 stages, lb(256,2)) which beat
// R9; (c) ldmatrix x4 fragment loads (6 LDSM vs 24 LDS per k32-step) to halve
// non-MMA issue slots. Mapping safety: R5(ldmatrix) == R6(LDS) bit-identical,
// and R8 proved that mapping correct.
// ============================================================================

static constexpr int BM = 128;
static constexpr int BN = 128;
static constexpr int BK = 128;
static constexpr int STAGES = 3;
static constexpr int K_DIM  = 4096;
static constexpr int N_OUT  = 11008;
static constexpr int M_ROWS = 8192;
static constexpr int NITER  = K_DIM / BK;            // 32
static constexpr int A_BYTES = BM * BK;              // 16384
static constexpr int STAGE_BYTES = (BM + BN) * BK;   // 32768
static constexpr int SMEM_TOTAL  = STAGES * STAGE_BYTES;   // 98304

static constexpr int X_ELEMS = M_ROWS * K_DIM;    // 33554432
static constexpr int W_ELEMS = N_OUT * K_DIM;     // 45088768
static constexpr int B_ELEMS = N_OUT;             // 11008

__device__ int8_t g_x[X_ELEMS];
__device__ int8_t g_w[W_ELEMS];

#define DI __device__ __forceinline__

DI uint32_t smem_u32(const void* p) {
    uint32_t a;
    asm("{ .reg .u64 t; cvta.to.shared.u64 t, %1; cvt.u32.u64 %0, t; }"
        : "=r"(a) : "l"(p));
    return a;
}

#define CP_ASYNC16(dst, src) \
    asm volatile("cp.async.cg.shared.global [%0], [%1], 16;" \
                 :: "r"((uint32_t)(dst)), "l"(src) : "memory")

#define CP_ASYNC_COMMIT() asm volatile("cp.async.commit_group;" ::: "memory")
#define CP_ASYNC_WAIT1()  asm volatile("cp.async.wait_group 1;" ::: "memory")
#define CP_ASYNC_WAIT0()  asm volatile("cp.async.wait_group 0;" ::: "memory")

#define LDSM_X4(r0, r1, r2, r3, addr) \
    asm volatile("ldmatrix.sync.aligned.m8n8.x4.shared.b16 {%0,%1,%2,%3}, [%4];" \
                 : "=r"(r0), "=r"(r1), "=r"(r2), "=r"(r3) : "r"(addr))

#define MMA_S8(d, a, b) \
    asm volatile("mma.sync.aligned.m16n8k32.row.col.s32.s8.s8.s32 " \
                 "{%0,%1,%2,%3},{%4,%5,%6,%7},{%8,%9},{%0,%1,%2,%3};" \
                 : "+r"((d)[0]), "+r"((d)[1]), "+r"((d)[2]), "+r"((d)[3]) \
                 : "r"((a)[0]), "r"((a)[1]), "r"((a)[2]), "r"((a)[3]), \
                   "r"((b)[0]), "r"((b)[1]))

// ---------------------------------------------------------------------------
// Pack with in-block encoding detection (deterministic; 1 launch per tensor).
// Each block scans the first 1024 words of src, classifies, then packs its
// 16B-per-thread slice. Modes: 1 = int32-widened, 2 = float32-widened,
// 0 = raw int8 passthrough.
// ---------------------------------------------------------------------------
__global__ void __launch_bounds__(256)
pack_kernel(int8_t* __restrict__ dst, const void* __restrict__ src, int n16)
{
    const uint32_t* p = (const uint32_t*)src;
    const int t = threadIdx.x;
    bool i32ok = true, f32ok = true;
    #pragma unroll
    for (int j = 0; j < 4; j++) {
        uint32_t u = p[t * 4 + j];
        int32_t vi = (int32_t)u;
        if (vi < -127 || vi > 127) i32ok = false;
        float vf = __uint_as_float(u);
        if (!(fabsf(vf) <= 127.0f) || truncf(vf) != vf) f32ok = false;
    }
    const int i32all = __syncthreads_and((int)i32ok);
    const int f32all = __syncthreads_and((int)f32ok);
    const int mode = i32all ? 1 : (f32all ? 2 : 0);

    const int i = blockIdx.x * blockDim.x + t;
    if (i >= n16) return;
    if (mode == 0) {
        ((int4*)dst)[i] = ((const int4*)src)[i];
    } else {
        union { int8_t b[16]; int4 v; } o;
        if (mode == 1) {
            const int* s = (const int*)src + (size_t)i * 16;
            #pragma unroll
            for (int j = 0; j < 16; j++) o.b[j] = (int8_t)s[j];
        } else {
            const float* s = (const float*)src + (size_t)i * 16;
            #pragma unroll
            for (int j = 0; j < 16; j++) o.b[j] = (int8_t)__float2int_rn(s[j]);
        }
        ((int4*)dst)[i] = o.v;
    }
}

// ---------------------------------------------------------------------------
// GEMM: IMMA m16n8k32, 128x128 tile, 3-stage cp.async ring, ldmatrix frags
// ---------------------------------------------------------------------------
__global__ void __launch_bounds__(256, 2)
w8a8_silu_kernel(const float* __restrict__ bias,
                 const float* __restrict__ alpha_p,
                 float*       __restrict__ out)
{
    extern __shared__ char smem[];
    const uint32_t sb = smem_u32(smem);
    const int tid  = threadIdx.x;
    const int lane = tid & 31;
    const int wid  = tid >> 5;
    const int warp_m = wid >> 2;      // 0..1
    const int warp_n = wid & 3;       // 0..3

    const size_t m0 = (size_t)blockIdx.x * BM;
    const size_t n0 = (size_t)blockIdx.y * BN;

    // cp.async src/dst precompute (4 x 16B of A and B per thread per stage)
    uint32_t a_dst[4], b_dst[4];
    const int8_t* a_src[4];
    const int8_t* b_src[4];
    #pragma unroll
    for (int i = 0; i < 4; i++) {
        int idx = tid + i * 256;
        int r = idx >> 3, seg = idx & 7;
        uint32_t col = (uint32_t)(seg * 16) ^ (uint32_t)((r & 7) << 4);
        a_dst[i] = r * 128 + col;
        b_dst[i] = A_BYTES + r * 128 + col;
        a_src[i] = g_x + (m0 + r) * (size_t)K_DIM + seg * 16;
        b_src[i] = g_w + (n0 + r) * (size_t)K_DIM + seg * 16;
    }

    // ---- ldmatrix address precompute ----
    // Common swizzle XOR: all ldmatrix row addresses have row%8 == lane%8.
    const uint32_t xorc = (uint32_t)((lane & 7) << 4);
    // A x4 (per mt): matrices (rows0-7,klo)(rows8-15,klo)(rows0-7,khi)(rows8-15,khi)
    //   row = warp_m*64 + mt*16 + ((lane>>3)&1)*8 + (lane&7); khalf=(lane>>4)*16
    uint32_t a_off[4];
    #pragma unroll
    for (int mt = 0; mt < 4; mt++) {
        int row = warp_m * 64 + mt * 16 + (((lane >> 3) & 1) << 3) + (lane & 7);
        a_off[mt] = (uint32_t)(row * 128);
    }
    const uint32_t akh = (uint32_t)((lane >> 4) * 16);
    // B x4 (per nt-pair p): matrices (nt=2p,klo)(2p,khi)(2p+1,klo)(2p+1,khi)
    //   row = warp_n*32 + (2p + (lane>>4))*8 + (lane&7); khalf=((lane>>3)&1)*16
    uint32_t b_off[2];
    #pragma unroll
    for (int p = 0; p < 2; p++) {
        int row = warp_n * 32 + (2 * p + (lane >> 4)) * 8 + (lane & 7);
        b_off[p] = (uint32_t)(A_BYTES + row * 128);
    }
    const uint32_t bkh = (uint32_t)(((lane >> 3) & 1) * 16);

    int acc[4][4][4];
    #pragma unroll
    for (int mt = 0; mt < 4; mt++)
        #pragma unroll
        for (int nt = 0; nt < 4; nt++)
            #pragma unroll
            for (int i = 0; i < 4; i++) acc[mt][nt][i] = 0;

    auto load_stage = [&](int s, int kt) {
        const uint32_t base = sb + s * STAGE_BYTES;
        const int ko = kt * BK;
        #pragma unroll
        for (int i = 0; i < 4; i++) CP_ASYNC16(base + a_dst[i], a_src[i] + ko);
        #pragma unroll
        for (int i = 0; i < 4; i++) CP_ASYNC16(base + b_dst[i], b_src[i] + ko);
    };

    load_stage(0, 0); CP_ASYNC_COMMIT();
    load_stage(1, 1); CP_ASYNC_COMMIT();

    for (int it = 0; it < NITER; it++) {
        CP_ASYNC_WAIT1();
        __syncthreads();

        if (it + 2 < NITER) load_stage((it + 2) % STAGES, it + 2);
        CP_ASYNC_COMMIT();

        const uint32_t stgb = sb + (it % STAGES) * STAGE_BYTES;
        #pragma unroll
        for (int ks = 0; ks < 4; ks++) {
            const uint32_t kcol = (uint32_t)(ks * 32);
            const uint32_t acol = (kcol + akh) ^ xorc;
            const uint32_t bcol = (kcol + bkh) ^ xorc;

            uint32_t af[4][4], bf[4][2];
            #pragma unroll
            for (int mt = 0; mt < 4; mt++)
                LDSM_X4(af[mt][0], af[mt][1], af[mt][2], af[mt][3],
                        stgb + a_off[mt] + acol);
            #pragma unroll
            for (int p = 0; p < 2; p++)
                LDSM_X4(bf[2 * p][0], bf[2 * p][1], bf[2 * p + 1][0], bf[2 * p + 1][1],
                        stgb + b_off[p] + bcol);

            #pragma unroll
            for (int mt = 0; mt < 4; mt++)
                #pragma unroll
                for (int nt = 0; nt < 4; nt++)
                    MMA_S8(acc[mt][nt], af[mt], bf[nt]);
        }
    }
    CP_ASYNC_WAIT0();

    // epilogue: dequant + bias + SiLU
    const float alpha = __ldg(alpha_p);
    const int groupID = lane >> 2;
    const int tg      = lane & 3;
    const float* bias_w = bias + n0 + warp_n * 32;
    float bv[4][2];
    #pragma unroll
    for (int nt = 0; nt < 4; nt++) {
        float2 b2 = *(const float2*)(bias_w + nt * 8 + tg * 2);
        bv[nt][0] = b2.x; bv[nt][1] = b2.y;
    }

    #pragma unroll
    for (int mt = 0; mt < 4; mt++) {
        #pragma unroll
        for (int h = 0; h < 2; h++) {
            const size_t row = m0 + warp_m * 64 + mt * 16 + groupID + h * 8;
            float* orow = out + row * (size_t)N_OUT + n0 + warp_n * 32;
            #pragma unroll
            for (int nt = 0; nt < 4; nt++) {
                float y0 = alpha * (float)acc[mt][nt][h * 2 + 0] + bv[nt][0];
                float y1 = alpha * (float)acc[mt][nt][h * 2 + 1] + bv[nt][1];
                y0 = y0 / (1.0f + __expf(-y0));
                y1 = y1 / (1.0f + __expf(-y1));
                *(float2*)(orow + nt * 8 + tg * 2) = make_float2(y0, y1);
            }
        }
    }
}

// ---------------------------------------------------------------------------
extern "C" void kernel_launch(void* const* d_in, const int* in_sizes, int n_in,
                              void* d_out, int out_size)
{
    // Identify inputs by element count (all four distinct); positional fallback.
    const void* px = nullptr; const void* pw = nullptr;
    const void* pb = nullptr; const void* pa = nullptr;
    for (int i = 0; i < n_in; i++) {
        switch (in_sizes[i]) {
            case X_ELEMS: px = d_in[i]; break;
            case W_ELEMS: pw = d_in[i]; break;
            case B_ELEMS: pb = d_in[i]; break;
            case 1:       pa = d_in[i]; break;
            default: break;
        }
    }
    if (!px || !pw || !pb || !pa) {
        px = d_in[0]; pw = d_in[1]; pb = d_in[2]; pa = d_in[3];
    }

    int8_t* gx; cudaGetSymbolAddress((void**)&gx, g_x);
    int8_t* gw; cudaGetSymbolAddress((void**)&gw, g_w);

    // Exactly 3 launches per call -> ncu -s 5 -c 1 captures the 2nd call's GEMM.
    const int xn16 = X_ELEMS / 16, wn16 = W_ELEMS / 16;
    pack_kernel<<<(xn16 + 255) / 256, 256>>>(gx, px, xn16);
    pack_kernel<<<(wn16 + 255) / 256, 256>>>(gw, pw, wn16);

    cudaFuncSetAttribute(w8a8_silu_kernel,
                         cudaFuncAttributeMaxDynamicSharedMemorySize, SMEM_TOTAL);
    dim3 grid(M_ROWS / BM, N_OUT / BN);   // (64, 86)
    w8a8_silu_kernel<<<grid, 256, SMEM_TOTAL>>>((const float*)pb, (const float*)pa,
                                                (float*)d_out);
}

// round 11
// speedup vs baseline: 1.6369x; 1.6369x over previous
#include <cuda_runtime.h>
#include <cstdint>
#include <math.h>

// ============================================================================
// W8A8 int8 GEMM + alpha/bias + SiLU -> fp32   (base sm_103 ISA: no tcgen05)
//   x [8192,4096] i8 (K-major), w [11008,4096] i8 (K-major), out [8192,11008] f32
//
// R11: observability round. GEMM reverted bit-for-bit to R8 (best: 5122us;
// R9 occupancy change and R10 ldmatrix both regressed). Launch structure is
// now detect(2,3,4=packs) then GEMM at global launch index 5 (2 harness
// prelaunches + 3 of mine) so ncu -s 5 -c 1 finally captures the GEMM, whose
// pipe split decides the next move (fp32-hybrid vs integer-dot ceiling).
// Evidence so far: GEMM time ~= 264 MAC/cyc/SM == dp4a-class rate ->
// mma.sync.s8 likely emulated at the scalar integer-dot ceiling.
// ============================================================================

static constexpr int BM = 128;
static constexpr int BN = 128;
static constexpr int BK = 128;
static constexpr int STAGES = 3;
static constexpr int K_DIM  = 4096;
static constexpr int N_OUT  = 11008;
static constexpr int M_ROWS = 8192;
static constexpr int NITER  = K_DIM / BK;            // 32
static constexpr int A_BYTES = BM * BK;              // 16384
static constexpr int STAGE_BYTES = (BM + BN) * BK;   // 32768
static constexpr int SMEM_TOTAL  = STAGES * STAGE_BYTES;   // 98304

static constexpr int X_ELEMS = M_ROWS * K_DIM;    // 33554432
static constexpr int W_ELEMS = N_OUT * K_DIM;     // 45088768
static constexpr int B_ELEMS = N_OUT;             // 11008

__device__ int8_t g_x[X_ELEMS];
__device__ int8_t g_w[W_ELEMS];
__device__ int    g_mode[2];   // 0 = raw int8, 1 = int32-widened, 2 = float32-widened

#define DI __device__ __forceinline__

DI uint32_t smem_u32(const void* p) {
    uint32_t a;
    asm("{ .reg .u64 t; cvta.to.shared.u64 t, %1; cvt.u32.u64 %0, t; }"
        : "=r"(a) : "l"(p));
    return a;
}

#define CP_ASYNC16(dst, src) \
    asm volatile("cp.async.cg.shared.global [%0], [%1], 16;" \
                 :: "r"((uint32_t)(dst)), "l"(src) : "memory")

#define CP_ASYNC_COMMIT() asm volatile("cp.async.commit_group;" ::: "memory")
#define CP_ASYNC_WAIT1()  asm volatile("cp.async.wait_group 1;" ::: "memory")
#define CP_ASYNC_WAIT0()  asm volatile("cp.async.wait_group 0;" ::: "memory")

#define MMA_S8(d, a, b) \
    asm volatile("mma.sync.aligned.m16n8k32.row.col.s32.s8.s8.s32 " \
                 "{%0,%1,%2,%3},{%4,%5,%6,%7},{%8,%9},{%0,%1,%2,%3};" \
                 : "+r"((d)[0]), "+r"((d)[1]), "+r"((d)[2]), "+r"((d)[3]) \
                 : "r"((a)[0]), "r"((a)[1]), "r"((a)[2]), "r"((a)[3]), \
                   "r"((b)[0]), "r"((b)[1]))

// ---------------------------------------------------------------------------
// Detect: one launch classifies both tensors. Block 0 -> x, block 1 -> w.
// 256 threads scan the first 1024 words; deterministic.
// ---------------------------------------------------------------------------
__global__ void detect_kernel(const void* __restrict__ px, const void* __restrict__ pw)
{
    const uint32_t* p = (const uint32_t*)(blockIdx.x == 0 ? px : pw);
    const int t = threadIdx.x;
    bool i32ok = true, f32ok = true;
    #pragma unroll
    for (int j = 0; j < 4; j++) {
        uint32_t u = p[t * 4 + j];
        int32_t vi = (int32_t)u;
        if (vi < -127 || vi > 127) i32ok = false;
        float vf = __uint_as_float(u);
        if (!(fabsf(vf) <= 127.0f) || truncf(vf) != vf) f32ok = false;
    }
    const int i32all = __syncthreads_and((int)i32ok);
    const int f32all = __syncthreads_and((int)f32ok);
    if (t == 0) g_mode[blockIdx.x] = i32all ? 1 : (f32all ? 2 : 0);
}

// ---------------------------------------------------------------------------
// Pack: normalize to int8 scratch. One thread = 16 output bytes.
// ---------------------------------------------------------------------------
__global__ void __launch_bounds__(256)
pack_kernel(int8_t* __restrict__ dst, const void* __restrict__ src, int n16, int slot)
{
    int i = blockIdx.x * blockDim.x + threadIdx.x;
    if (i >= n16) return;
    const int mode = g_mode[slot];
    if (mode == 0) {
        ((int4*)dst)[i] = ((const int4*)src)[i];
    } else {
        union { int8_t b[16]; int4 v; } o;
        if (mode == 1) {
            const int* s = (const int*)src + (size_t)i * 16;
            #pragma unroll
            for (int j = 0; j < 16; j++) o.b[j] = (int8_t)s[j];
        } else {
            const float* s = (const float*)src + (size_t)i * 16;
            #pragma unroll
            for (int j = 0; j < 16; j++) o.b[j] = (int8_t)__float2int_rn(s[j]);
        }
        ((int4*)dst)[i] = o.v;
    }
}

// ---------------------------------------------------------------------------
// GEMM (R8 verbatim): IMMA m16n8k32, 128x128 tile, 3-stage ring, direct LDS
// ---------------------------------------------------------------------------
__global__ void __launch_bounds__(256, 2)
w8a8_silu_kernel(const float* __restrict__ bias,
                 const float* __restrict__ alpha_p,
                 float*       __restrict__ out)
{
    extern __shared__ char smem[];
    const uint32_t sb = smem_u32(smem);
    const int tid  = threadIdx.x;
    const int lane = tid & 31;
    const int wid  = tid >> 5;
    const int warp_m = wid >> 2;
    const int warp_n = wid & 3;

    const size_t m0 = (size_t)blockIdx.x * BM;
    const size_t n0 = (size_t)blockIdx.y * BN;

    // cp.async src/dst precompute (4 x 16B of A and B per thread per stage)
    uint32_t a_dst[4], b_dst[4];
    const int8_t* a_src[4];
    const int8_t* b_src[4];
    #pragma unroll
    for (int i = 0; i < 4; i++) {
        int idx = tid + i * 256;
        int r = idx >> 3, seg = idx & 7;
        uint32_t col = (uint32_t)(seg * 16) ^ (uint32_t)((r & 7) << 4);
        a_dst[i] = r * 128 + col;
        b_dst[i] = A_BYTES + r * 128 + col;
        a_src[i] = g_x + (m0 + r) * (size_t)K_DIM + seg * 16;
        b_src[i] = g_w + (n0 + r) * (size_t)K_DIM + seg * 16;
    }

    // fragment bases: all fragment rows == lane>>2 (mod 8) -> one XOR constant
    const uint32_t X   = (uint32_t)((lane >> 2) << 4);
    const uint32_t tg4 = (uint32_t)((lane & 3) << 2);
    const uint32_t oa = (uint32_t)((warp_m * 64 + (lane >> 2)) * 128) + tg4;
    const uint32_t ob = (uint32_t)(A_BYTES + (warp_n * 32 + (lane >> 2)) * 128) + tg4;

    int acc[4][4][4];
    #pragma unroll
    for (int mt = 0; mt < 4; mt++)
        #pragma unroll
        for (int nt = 0; nt < 4; nt++)
            #pragma unroll
            for (int i = 0; i < 4; i++) acc[mt][nt][i] = 0;

    auto load_stage = [&](int s, int kt) {
        const uint32_t base = sb + s * STAGE_BYTES;
        const int ko = kt * BK;
        #pragma unroll
        for (int i = 0; i < 4; i++) CP_ASYNC16(base + a_dst[i], a_src[i] + ko);
        #pragma unroll
        for (int i = 0; i < 4; i++) CP_ASYNC16(base + b_dst[i], b_src[i] + ko);
    };

    load_stage(0, 0); CP_ASYNC_COMMIT();
    load_stage(1, 1); CP_ASYNC_COMMIT();

    for (int it = 0; it < NITER; it++) {
        CP_ASYNC_WAIT1();
        __syncthreads();

        if (it + 2 < NITER) load_stage((it + 2) % STAGES, it + 2);
        CP_ASYNC_COMMIT();

        const char* stg = smem + (it % STAGES) * STAGE_BYTES;
        #pragma unroll
        for (int ks = 0; ks < 4; ks++) {
            const uint32_t slo = ((uint32_t)(ks * 32)) ^ X;
            const uint32_t shi = slo ^ 16u;

            uint32_t af[4][4], bf[4][2];
            #pragma unroll
            for (int mt = 0; mt < 4; mt++) {
                const char* pa = stg + oa + mt * 2048;
                af[mt][0] = *(const uint32_t*)(pa + slo);
                af[mt][1] = *(const uint32_t*)(pa + slo + 1024);
                af[mt][2] = *(const uint32_t*)(pa + shi);
                af[mt][3] = *(const uint32_t*)(pa + shi + 1024);
            }
            #pragma unroll
            for (int nt = 0; nt < 4; nt++) {
                const char* pb = stg + ob + nt * 1024;
                bf[nt][0] = *(const uint32_t*)(pb + slo);
                bf[nt][1] = *(const uint32_t*)(pb + shi);
            }
            #pragma unroll
            for (int mt = 0; mt < 4; mt++)
                #pragma unroll
                for (int nt = 0; nt < 4; nt++)
                    MMA_S8(acc[mt][nt], af[mt], bf[nt]);
        }
    }
    CP_ASYNC_WAIT0();

    // epilogue: dequant + bias + SiLU
    const float alpha = __ldg(alpha_p);
    const int groupID = lane >> 2;
    const int tg      = lane & 3;
    const float* bias_w = bias + n0 + warp_n * 32;
    float bv[4][2];
    #pragma unroll
    for (int nt = 0; nt < 4; nt++) {
        float2 b2 = *(const float2*)(bias_w + nt * 8 + tg * 2);
        bv[nt][0] = b2.x; bv[nt][1] = b2.y;
    }

    #pragma unroll
    for (int mt = 0; mt < 4; mt++) {
        #pragma unroll
        for (int h = 0; h < 2; h++) {
            const size_t row = m0 + warp_m * 64 + mt * 16 + groupID + h * 8;
            float* orow = out + row * (size_t)N_OUT + n0 + warp_n * 32;
            #pragma unroll
            for (int nt = 0; nt < 4; nt++) {
                float y0 = alpha * (float)acc[mt][nt][h * 2 + 0] + bv[nt][0];
                float y1 = alpha * (float)acc[mt][nt][h * 2 + 1] + bv[nt][1];
                y0 = y0 / (1.0f + __expf(-y0));
                y1 = y1 / (1.0f + __expf(-y1));
                *(float2*)(orow + nt * 8 + tg * 2) = make_float2(y0, y1);
            }
        }
    }
}

// ---------------------------------------------------------------------------
extern "C" void kernel_launch(void* const* d_in, const int* in_sizes, int n_in,
                              void* d_out, int out_size)
{
    // Identify inputs by element count (all four distinct); positional fallback.
    const void* px = nullptr; const void* pw = nullptr;
    const void* pb = nullptr; const void* pa = nullptr;
    for (int i = 0; i < n_in; i++) {
        switch (in_sizes[i]) {
            case X_ELEMS: px = d_in[i]; break;
            case W_ELEMS: pw = d_in[i]; break;
            case B_ELEMS: pb = d_in[i]; break;
            case 1:       pa = d_in[i]; break;
            default: break;
        }
    }
    if (!px || !pw || !pb || !pa) {
        px = d_in[0]; pw = d_in[1]; pb = d_in[2]; pa = d_in[3];
    }

    int8_t* gx; cudaGetSymbolAddress((void**)&gx, g_x);
    int8_t* gw; cudaGetSymbolAddress((void**)&gw, g_w);

    // Exactly 4 launches: detect, pack-x, pack-w, GEMM.
    // With the 2 harness prelaunches this puts the GEMM at global index 5,
    // where ncu -s 5 -c 1 samples.
    detect_kernel<<<2, 256>>>(px, pw);
    const int xn16 = X_ELEMS / 16, wn16 = W_ELEMS / 16;
    pack_kernel<<<(xn16 + 255) / 256, 256>>>(gx, px, xn16, 0);
    pack_kernel<<<(wn16 + 255) / 256, 256>>>(gw, pw, wn16, 1);

    cudaFuncSetAttribute(w8a8_silu_kernel,
                         cudaFuncAttributeMaxDynamicSharedMemorySize, SMEM_TOTAL);
    dim3 grid(M_ROWS / BM, N_OUT / BN);   // (64, 86)
    w8a8_silu_kernel<<<grid, 256, SMEM_TOTAL>>>((const float*)pb, (const float*)pa,
                                                (float*)d_out);
}